// round 8
// baseline (speedup 1.0000x reference)
#include <cuda_runtime.h>
#include <math.h>

#define B_SZ 64
#define N_SZ 4096
#define D_SZ 256
#define TEMPERATURE 0.1f
#define EPS 1e-8f

// Packed cross-block accumulator:
//   bits [0:52)  : sum of per-sample losses in fixed point (x 2^32)
//   bits [52:59) : arrival count (0..64)
// Integer adds commute exactly -> deterministic result, no ordering needed.
// Last arriver resets it to 0 for the next graph replay.
__device__ unsigned long long g_pack = 0ULL;

#define COUNT_ONE   (1ULL << 52)
#define SUM_MASK    ((1ULL << 52) - 1ULL)
#define FIXED_SCALE 4294967296.0f   /* 2^32 */

__global__ __launch_bounds__(32, 1)
void graph_contrastive_loss_kernel(const float* __restrict__ emb,
                                   const int* __restrict__ anchor_idx,
                                   const int* __restrict__ pos_idx,
                                   const int* __restrict__ neg_graph_idx,
                                   const int* __restrict__ neg_node_idx,
                                   float* __restrict__ out) {
    const int s    = blockIdx.x;      // one sample per block, one warp per block
    const int lane = threadIdx.x;     // 0..31

    // Index loads: all lanes hit the same addresses -> broadcast, 1 latency trip.
    const int ai = __ldg(anchor_idx + s);
    const int pi = __ldg(pos_idx + s);
    const int ng = __ldg(neg_graph_idx + s);
    const int ni = __ldg(neg_node_idx + s);

    const float4* A  = reinterpret_cast<const float4*>(
        emb + ((size_t)s  * N_SZ + ai) * D_SZ);
    const float4* P  = reinterpret_cast<const float4*>(
        emb + ((size_t)s  * N_SZ + pi) * D_SZ);
    const float4* Ng = reinterpret_cast<const float4*>(
        emb + ((size_t)ng * N_SZ + ni) * D_SZ);

    // D=256 floats = 64 float4; 32 lanes -> 2 float4 per vector per lane.
    // Issue all 6 loads up front (MLP=6), then consume.
    const float4 av0 = A[lane];
    const float4 pv0 = P[lane];
    const float4 nv0 = Ng[lane];
    const float4 av1 = A[lane + 32];
    const float4 pv1 = P[lane + 32];
    const float4 nv1 = Ng[lane + 32];

    float ap, an, aa, pp, nn;
    ap  = av0.x * pv0.x + av0.y * pv0.y + av0.z * pv0.z + av0.w * pv0.w;
    ap += av1.x * pv1.x + av1.y * pv1.y + av1.z * pv1.z + av1.w * pv1.w;
    an  = av0.x * nv0.x + av0.y * nv0.y + av0.z * nv0.z + av0.w * nv0.w;
    an += av1.x * nv1.x + av1.y * nv1.y + av1.z * nv1.z + av1.w * nv1.w;
    aa  = av0.x * av0.x + av0.y * av0.y + av0.z * av0.z + av0.w * av0.w;
    aa += av1.x * av1.x + av1.y * av1.y + av1.z * av1.z + av1.w * av1.w;
    pp  = pv0.x * pv0.x + pv0.y * pv0.y + pv0.z * pv0.z + pv0.w * pv0.w;
    pp += pv1.x * pv1.x + pv1.y * pv1.y + pv1.z * pv1.z + pv1.w * pv1.w;
    nn  = nv0.x * nv0.x + nv0.y * nv0.y + nv0.z * nv0.z + nv0.w * nv0.w;
    nn += nv1.x * nv1.x + nv1.y * nv1.y + nv1.z * nv1.z + nv1.w * nv1.w;

    #pragma unroll
    for (int off = 16; off > 0; off >>= 1) {
        ap += __shfl_down_sync(0xFFFFFFFFu, ap, off);
        an += __shfl_down_sync(0xFFFFFFFFu, an, off);
        aa += __shfl_down_sync(0xFFFFFFFFu, aa, off);
        pp += __shfl_down_sync(0xFFFFFFFFu, pp, off);
        nn += __shfl_down_sync(0xFFFFFFFFu, nn, off);
    }

    if (lane == 0) {
        const float na = fmaxf(sqrtf(aa), EPS);
        const float np = fmaxf(sqrtf(pp), EPS);
        const float nq = fmaxf(sqrtf(nn), EPS);
        const float pos_sim = (ap / (na * np)) / TEMPERATURE;
        const float neg_sim = (an / (na * nq)) / TEMPERATURE;
        const float d = neg_sim - pos_sim;
        // logaddexp(0, d) >= 0, numerically stable
        const float loss = fmaxf(d, 0.f) + log1pf(expf(-fabsf(d)));

        // Fixed-point quantization: exact-commuting integer accumulation.
        const long long q = llrintf(loss * FIXED_SCALE);
        const unsigned long long my = COUNT_ONE + (unsigned long long)q;
        const unsigned long long prev = atomicAdd(&g_pack, my);

        if ((prev >> 52) == (unsigned long long)(B_SZ - 1)) {
            // I'm the last arriver: total sum = prev's sum field + my own.
            const unsigned long long total =
                (prev & SUM_MASK) + (unsigned long long)q;
            out[0] = (float)((double)total *
                             (1.0 / ((double)FIXED_SCALE * (double)B_SZ)));
            g_pack = 0ULL;   // reset for next graph replay (all adds are done)
        }
    }
}

extern "C" void kernel_launch(void* const* d_in, const int* in_sizes, int n_in,
                              void* d_out, int out_size) {
    const float* emb           = (const float*)d_in[0];
    // d_in[1] = graph_labels (unused by the loss)
    const int*   anchor_idx    = (const int*)d_in[2];
    const int*   pos_idx       = (const int*)d_in[3];
    const int*   neg_graph_idx = (const int*)d_in[4];
    const int*   neg_node_idx  = (const int*)d_in[5];
    float*       out           = (float*)d_out;

    graph_contrastive_loss_kernel<<<B_SZ, 32>>>(
        emb, anchor_idx, pos_idx, neg_graph_idx, neg_node_idx, out);
}

// round 9
// speedup vs baseline: 1.0047x; 1.0047x over previous
#include <cuda_runtime.h>
#include <math.h>

#define B_SZ 64
#define N_SZ 4096
#define D_SZ 256
#define INV_TEMP 10.0f
#define EPS 1e-8f

// Packed cross-block accumulator:
//   bits [0:52)  : sum of per-sample losses, fixed point (x 2^32)
//   bits [52:59) : arrival count (0..64)
// Integer adds commute exactly -> deterministic. Last arriver resets for replay.
__device__ unsigned long long g_pack = 0ULL;

#define COUNT_ONE   (1ULL << 52)
#define SUM_MASK    ((1ULL << 52) - 1ULL)
#define FIXED_SCALE 4294967296.0f   /* 2^32 */

__global__ __launch_bounds__(32, 1)
void graph_contrastive_loss_kernel(const float* __restrict__ emb,
                                   const int* __restrict__ anchor_idx,
                                   const int* __restrict__ pos_idx,
                                   const int* __restrict__ neg_graph_idx,
                                   const int* __restrict__ neg_node_idx,
                                   float* __restrict__ out) {
    const int s    = blockIdx.x;      // one sample per block, one warp per block
    const int lane = threadIdx.x;     // 0..31

    // 4 independent broadcast index loads (one latency trip, MLP=4).
    const int ai = __ldg(anchor_idx + s);
    const int pi = __ldg(pos_idx + s);
    const int ng = __ldg(neg_graph_idx + s);
    const int ni = __ldg(neg_node_idx + s);

    const float4* A  = reinterpret_cast<const float4*>(
        emb + ((size_t)s  * N_SZ + ai) * D_SZ);
    const float4* P  = reinterpret_cast<const float4*>(
        emb + ((size_t)s  * N_SZ + pi) * D_SZ);
    const float4* Ng = reinterpret_cast<const float4*>(
        emb + ((size_t)ng * N_SZ + ni) * D_SZ);

    // D=256 floats = 64 float4; 32 lanes -> 2 float4 per vector per lane.
    // All 6 gathers front-batched (MLP=6), then consumed.
    const float4 av0 = A[lane];
    const float4 pv0 = P[lane];
    const float4 nv0 = Ng[lane];
    const float4 av1 = A[lane + 32];
    const float4 pv1 = P[lane + 32];
    const float4 nv1 = Ng[lane + 32];

    float ap, an, aa, pp, nn;
    ap  = av0.x * pv0.x + av0.y * pv0.y + av0.z * pv0.z + av0.w * pv0.w;
    ap += av1.x * pv1.x + av1.y * pv1.y + av1.z * pv1.z + av1.w * pv1.w;
    an  = av0.x * nv0.x + av0.y * nv0.y + av0.z * nv0.z + av0.w * nv0.w;
    an += av1.x * nv1.x + av1.y * nv1.y + av1.z * nv1.z + av1.w * nv1.w;
    aa  = av0.x * av0.x + av0.y * av0.y + av0.z * av0.z + av0.w * av0.w;
    aa += av1.x * av1.x + av1.y * av1.y + av1.z * av1.z + av1.w * av1.w;
    pp  = pv0.x * pv0.x + pv0.y * pv0.y + pv0.z * pv0.z + pv0.w * pv0.w;
    pp += pv1.x * pv1.x + pv1.y * pv1.y + pv1.z * pv1.z + pv1.w * pv1.w;
    nn  = nv0.x * nv0.x + nv0.y * nv0.y + nv0.z * nv0.z + nv0.w * nv0.w;
    nn += nv1.x * nv1.x + nv1.y * nv1.y + nv1.z * nv1.z + nv1.w * nv1.w;

    // Butterfly reduction: all lanes end with the full sums (lane 0 used).
    #pragma unroll
    for (int off = 16; off > 0; off >>= 1) {
        ap += __shfl_xor_sync(0xFFFFFFFFu, ap, off);
        an += __shfl_xor_sync(0xFFFFFFFFu, an, off);
        aa += __shfl_xor_sync(0xFFFFFFFFu, aa, off);
        pp += __shfl_xor_sync(0xFFFFFFFFu, pp, off);
        nn += __shfl_xor_sync(0xFFFFFFFFu, nn, off);
    }

    if (lane == 0) {
        // cosine / temperature via rsqrt (norms ~16 >> EPS; clamp preserved
        // by flooring the squared norms at EPS^2).
        const float raa = rsqrtf(fmaxf(aa, EPS * EPS));
        const float rpp = rsqrtf(fmaxf(pp, EPS * EPS));
        const float rnn = rsqrtf(fmaxf(nn, EPS * EPS));
        const float pos_sim = ap * raa * rpp * INV_TEMP;
        const float neg_sim = an * raa * rnn * INV_TEMP;
        const float d = neg_sim - pos_sim;
        // softplus(d) = max(d,0) + log(1 + exp(-|d|)); arg of log in (1,2].
        const float loss = fmaxf(d, 0.f) + __logf(1.f + __expf(-fabsf(d)));

        // Exact-commuting fixed-point accumulation + arrival count, one atomic.
        const long long q = llrintf(loss * FIXED_SCALE);
        const unsigned long long my = COUNT_ONE + (unsigned long long)q;
        const unsigned long long prev = atomicAdd(&g_pack, my);

        if ((prev >> 52) == (unsigned long long)(B_SZ - 1)) {
            const unsigned long long total =
                (prev & SUM_MASK) + (unsigned long long)q;
            out[0] = (float)((double)total *
                             (1.0 / ((double)FIXED_SCALE * (double)B_SZ)));
            g_pack = 0ULL;   // reset for next graph replay (all adds done)
        }
    }
}

extern "C" void kernel_launch(void* const* d_in, const int* in_sizes, int n_in,
                              void* d_out, int out_size) {
    const float* emb           = (const float*)d_in[0];
    // d_in[1] = graph_labels (unused by the loss)
    const int*   anchor_idx    = (const int*)d_in[2];
    const int*   pos_idx       = (const int*)d_in[3];
    const int*   neg_graph_idx = (const int*)d_in[4];
    const int*   neg_node_idx  = (const int*)d_in[5];
    float*       out           = (float*)d_out;

    graph_contrastive_loss_kernel<<<B_SZ, 32>>>(
        emb, anchor_idx, pos_idx, neg_graph_idx, neg_node_idx, out);
}

// round 11
// speedup vs baseline: 1.0854x; 1.0804x over previous
#include <cuda_runtime.h>
#include <math.h>

#define B_SZ 64
#define N_SZ 4096
#define D_SZ 256
#define INV_TEMP 10.0f
#define EPS 1e-8f

// Packed cross-block accumulator:
//   bits [0:52)  : sum of per-sample losses, fixed point (x 2^32)
//   bits [52:59) : arrival count (0..64)
// Integer adds commute exactly -> deterministic. Last arriver resets for replay.
__device__ unsigned long long g_pack = 0ULL;

#define COUNT_ONE   (1ULL << 52)
#define SUM_MASK    ((1ULL << 52) - 1ULL)
#define FIXED_SCALE 4294967296.0f   /* 2^32 */

__global__ __launch_bounds__(32, 1)
void graph_contrastive_loss_kernel(const float* __restrict__ emb,
                                   const int* __restrict__ anchor_idx,
                                   const int* __restrict__ pos_idx,
                                   const int* __restrict__ neg_graph_idx,
                                   const int* __restrict__ neg_node_idx,
                                   float* __restrict__ out) {
    const int s    = blockIdx.x;      // one sample per block, one warp per block
    const int lane = threadIdx.x;     // 0..31

    // 4 independent broadcast index loads (one latency trip, MLP=4).
    const int ai = __ldg(anchor_idx + s);
    const int pi = __ldg(pos_idx + s);
    const int ng = __ldg(neg_graph_idx + s);
    const int ni = __ldg(neg_node_idx + s);

    const float4* A  = reinterpret_cast<const float4*>(
        emb + ((size_t)s  * N_SZ + ai) * D_SZ);
    const float4* P  = reinterpret_cast<const float4*>(
        emb + ((size_t)s  * N_SZ + pi) * D_SZ);
    const float4* Ng = reinterpret_cast<const float4*>(
        emb + ((size_t)ng * N_SZ + ni) * D_SZ);

    // D=256 floats = 64 float4; 32 lanes -> 2 float4 per vector per lane.
    // All 6 gathers front-batched (MLP=6), then consumed.
    const float4 av0 = A[lane];
    const float4 pv0 = P[lane];
    const float4 nv0 = Ng[lane];
    const float4 av1 = A[lane + 32];
    const float4 pv1 = P[lane + 32];
    const float4 nv1 = Ng[lane + 32];

    float ap, an, aa, pp, nn;
    ap  = av0.x * pv0.x + av0.y * pv0.y + av0.z * pv0.z + av0.w * pv0.w;
    ap += av1.x * pv1.x + av1.y * pv1.y + av1.z * pv1.z + av1.w * pv1.w;
    an  = av0.x * nv0.x + av0.y * nv0.y + av0.z * nv0.z + av0.w * nv0.w;
    an += av1.x * nv1.x + av1.y * nv1.y + av1.z * nv1.z + av1.w * nv1.w;
    aa  = av0.x * av0.x + av0.y * av0.y + av0.z * av0.z + av0.w * av0.w;
    aa += av1.x * av1.x + av1.y * av1.y + av1.z * av1.z + av1.w * av1.w;
    pp  = pv0.x * pv0.x + pv0.y * pv0.y + pv0.z * pv0.z + pv0.w * pv0.w;
    pp += pv1.x * pv1.x + pv1.y * pv1.y + pv1.z * pv1.z + pv1.w * pv1.w;
    nn  = nv0.x * nv0.x + nv0.y * nv0.y + nv0.z * nv0.z + nv0.w * nv0.w;
    nn += nv1.x * nv1.x + nv1.y * nv1.y + nv1.z * nv1.z + nv1.w * nv1.w;

    // Butterfly reduction: 5 independent chains, pipelined; all lanes end
    // with the full sums (no redux.f32 on sm_103a -- ptxas rejects it).
    #pragma unroll
    for (int off = 16; off > 0; off >>= 1) {
        ap += __shfl_xor_sync(0xFFFFFFFFu, ap, off);
        an += __shfl_xor_sync(0xFFFFFFFFu, an, off);
        aa += __shfl_xor_sync(0xFFFFFFFFu, aa, off);
        pp += __shfl_xor_sync(0xFFFFFFFFu, pp, off);
        nn += __shfl_xor_sync(0xFFFFFFFFu, nn, off);
    }

    // Scalar epilogue on ALL lanes (uniform data, no branch setup in front
    // of the MUFU chain). Norms ~16 >> EPS; clamp preserved via EPS^2 floor.
    const float raa = rsqrtf(fmaxf(aa, EPS * EPS));
    const float rpp = rsqrtf(fmaxf(pp, EPS * EPS));
    const float rnn = rsqrtf(fmaxf(nn, EPS * EPS));
    const float pos_sim = ap * raa * rpp * INV_TEMP;
    const float neg_sim = an * raa * rnn * INV_TEMP;
    const float d = neg_sim - pos_sim;
    // softplus(d) = max(d,0) + log(1 + exp(-|d|)); arg of log in (1,2].
    const float loss = fmaxf(d, 0.f) + __logf(1.f + __expf(-fabsf(d)));

    if (lane == 0) {
        // Exact-commuting fixed-point accumulation + arrival count, one atomic.
        const long long q = llrintf(loss * FIXED_SCALE);
        const unsigned long long my = COUNT_ONE + (unsigned long long)q;
        const unsigned long long prev = atomicAdd(&g_pack, my);

        if ((prev >> 52) == (unsigned long long)(B_SZ - 1)) {
            const unsigned long long total =
                (prev & SUM_MASK) + (unsigned long long)q;
            out[0] = (float)((double)total *
                             (1.0 / ((double)FIXED_SCALE * (double)B_SZ)));
            g_pack = 0ULL;   // reset for next graph replay (all adds done)
        }
    }
}

extern "C" void kernel_launch(void* const* d_in, const int* in_sizes, int n_in,
                              void* d_out, int out_size) {
    const float* emb           = (const float*)d_in[0];
    // d_in[1] = graph_labels (unused by the loss)
    const int*   anchor_idx    = (const int*)d_in[2];
    const int*   pos_idx       = (const int*)d_in[3];
    const int*   neg_graph_idx = (const int*)d_in[4];
    const int*   neg_node_idx  = (const int*)d_in[5];
    float*       out           = (float*)d_out;

    graph_contrastive_loss_kernel<<<B_SZ, 32>>>(
        emb, anchor_idx, pos_idx, neg_graph_idx, neg_node_idx, out);
}